// round 3
// baseline (speedup 1.0000x reference)
#include <cuda_runtime.h>
#include <cstdint>

#define NB 64
#define NC 512
#define NHW 768
#define NT 32
#define NPROTO 4000
#define NCLASS 4001

// ---------------- scratch (static device globals; no allocation) ----------------
__device__ float g_C[NT * NB * NC];        // pooled features, [t][b][c]
__device__ float g_GIC[NT * NB * 3 * NC];  // C_t @ Wihc^T + b_ih, [t*64+b][1536]
__device__ float g_GP[NB * 6 * NC];        // per-step: gi_prev (1536) | gh (1536)
__device__ float g_h[2][NB * NC];          // double-buffered hidden state
__device__ unsigned long long g_amax[2][NB];  // packed (ordered_val<<32 | ~class)

__device__ __forceinline__ unsigned ford(float f) {
    unsigned u = __float_as_uint(f);
    return (u & 0x80000000u) ? ~u : (u | 0x80000000u);
}

// ---------------- 1) attention pooling: C[t,b,c] = sum_hw feat[b,c,hw]*A[b,t,hw] ----
// grid (64 b, 8 c-chunks), 256 threads, dynamic smem = A[b] (32x768) + one feat row
__global__ __launch_bounds__(256) void pool_kernel(const float* __restrict__ feature,
                                                   const float* __restrict__ A) {
    extern __shared__ float sm[];
    float* As = sm;               // 32*768
    float* feats = sm + NT * NHW; // 768
    int b = blockIdx.x, cch = blockIdx.y;
    const float* Ab = A + (size_t)b * NT * NHW;
    for (int i = threadIdx.x; i < NT * NHW; i += 256) As[i] = Ab[i];
    __syncthreads();
    int t = threadIdx.x >> 3;  // 0..31
    int s = threadIdx.x & 7;   // 0..7
    for (int ci = 0; ci < 64; ci++) {
        int c = cch * 64 + ci;
        const float* fr = feature + ((size_t)b * NC + c) * NHW;
        __syncthreads();
        for (int i = threadIdx.x; i < NHW; i += 256) feats[i] = fr[i];
        __syncthreads();
        float acc = 0.f;
        const float* At = As + t * NHW;
        for (int i = s; i < NHW; i += 8) acc += feats[i] * At[i];
        acc += __shfl_down_sync(0xffffffffu, acc, 4);
        acc += __shfl_down_sync(0xffffffffu, acc, 2);
        acc += __shfl_down_sync(0xffffffffu, acc, 1);
        if (s == 0) g_C[((size_t)t * NB + b) * NC + c] = acc;
    }
}

// ---------------- 2) GIC = C2d[2048,512] @ Wihc^T[512,1536] + b_ih ------------------
// Mtile=64, Ntile=32, KC=16, 256 threads, 4x2 register tile. grid (32, 48)
__global__ __launch_bounds__(256) void gic_kernel(const float* __restrict__ W_ih,
                                                  const float* __restrict__ b_ih) {
    __shared__ float Xs[64][17];
    __shared__ float Ws[32][17];
    int m0 = blockIdx.x * 64;
    int n0 = blockIdx.y * 32;
    int tid = threadIdx.x;
    int ty = tid >> 4, tx = tid & 15;
    float acc[4][2] = {};
    const float* Cb = g_C + (size_t)m0 * NC;
    for (int k0 = 0; k0 < NC; k0 += 16) {
#pragma unroll
        for (int i = 0; i < 4; i++) {
            int lin = tid + i * 256, r = lin >> 4, k = lin & 15;
            Xs[r][k] = Cb[(size_t)r * NC + k0 + k];
        }
#pragma unroll
        for (int i = 0; i < 2; i++) {
            int lin = tid + i * 256, r = lin >> 4, k = lin & 15;
            Ws[r][k] = W_ih[(size_t)(n0 + r) * (2 * NC) + k0 + k];
        }
        __syncthreads();
#pragma unroll
        for (int kk = 0; kk < 16; kk++) {
            float xv[4], wv[2];
#pragma unroll
            for (int m = 0; m < 4; m++) xv[m] = Xs[ty + 16 * m][kk];
#pragma unroll
            for (int n = 0; n < 2; n++) wv[n] = Ws[tx + 16 * n][kk];
#pragma unroll
            for (int m = 0; m < 4; m++)
#pragma unroll
                for (int n = 0; n < 2; n++) acc[m][n] += xv[m] * wv[n];
        }
        __syncthreads();
    }
#pragma unroll
    for (int m = 0; m < 4; m++)
#pragma unroll
        for (int n = 0; n < 2; n++) {
            int row = m0 + ty + 16 * m;
            int g = n0 + tx + 16 * n;
            g_GIC[(size_t)row * 1536 + g] = acc[m][n] + b_ih[g];
        }
}

// ---------------- 3a) per-step gates: GP[64,3072] ----------------------------------
// cols [0,1536): prev @ Wihp^T ; cols [1536,3072): h_old @ Whh^T. grid 96 blocks.
__global__ __launch_bounds__(256) void gates_kernel(const float* __restrict__ semb,
                                                    const float* __restrict__ UNK,
                                                    const float* __restrict__ STA,
                                                    const float* __restrict__ W_ih,
                                                    const float* __restrict__ W_hh,
                                                    int t) {
    int c0 = blockIdx.x * 32;
    bool isP = (c0 < 1536);
    int tid = threadIdx.x;

    if (!isP && t == 0) {  // h_old == 0 -> gh part is exactly 0
        for (int i = tid; i < 64 * 32; i += 256) {
            int r = i >> 5, c = i & 31;
            g_GP[(size_t)r * 3072 + c0 + c] = 0.f;
        }
        return;
    }

    __shared__ float Xs[64][17];
    __shared__ float Ws[32][17];
    __shared__ int s_idx[64];
    if (isP && t > 0 && tid < 64) {
        unsigned long long p = g_amax[(t + 1) & 1][tid];
        s_idx[tid] = (int)(~(unsigned)(p & 0xffffffffULL));
    }
    __syncthreads();

    const float* h_old = g_h[(t + 1) & 1];
    int ty = tid >> 4, tx = tid & 15;
    float acc[4][2] = {};

    for (int k0 = 0; k0 < NC; k0 += 16) {
#pragma unroll
        for (int i = 0; i < 4; i++) {
            int lin = tid + i * 256, r = lin >> 4, k = lin & 15;
            int kg = k0 + k;
            float v;
            if (isP) {
                if (t == 0) v = STA[kg];
                else {
                    int idx = s_idx[r];
                    v = (idx < NPROTO) ? semb[(size_t)idx * NC + kg] : UNK[kg];
                }
            } else {
                v = h_old[(size_t)r * NC + kg];
            }
            Xs[r][k] = v;
        }
#pragma unroll
        for (int i = 0; i < 2; i++) {
            int lin = tid + i * 256, r = lin >> 4, k = lin & 15;
            float w;
            if (isP) w = W_ih[(size_t)(c0 + r) * (2 * NC) + NC + k0 + k];
            else     w = W_hh[(size_t)(c0 - 1536 + r) * NC + k0 + k];
            Ws[r][k] = w;
        }
        __syncthreads();
#pragma unroll
        for (int kk = 0; kk < 16; kk++) {
            float xv[4], wv[2];
#pragma unroll
            for (int m = 0; m < 4; m++) xv[m] = Xs[ty + 16 * m][kk];
#pragma unroll
            for (int n = 0; n < 2; n++) wv[n] = Ws[tx + 16 * n][kk];
#pragma unroll
            for (int m = 0; m < 4; m++)
#pragma unroll
                for (int n = 0; n < 2; n++) acc[m][n] += xv[m] * wv[n];
        }
        __syncthreads();
    }
#pragma unroll
    for (int m = 0; m < 4; m++)
#pragma unroll
        for (int n = 0; n < 2; n++) {
            int row = ty + 16 * m;
            int c = c0 + tx + 16 * n;
            g_GP[(size_t)row * 3072 + c] = acc[m][n];
        }
}

// ---------------- 3b) GRU combine -> h_new; also resets this step's argmax buf -----
__global__ __launch_bounds__(256) void combine_kernel(const float* __restrict__ b_hh,
                                                      int t) {
    int i = blockIdx.x * 256 + threadIdx.x;  // 0..32767
    int b = i >> 9, j = i & 511;
    const float* gic = g_GIC + ((size_t)t * NB + b) * 1536;
    const float* gp = g_GP + (size_t)b * 3072;
    float ir = gic[j] + gp[j];
    float iz = gic[j + 512] + gp[j + 512];
    float in_ = gic[j + 1024] + gp[j + 1024];
    float hr = gp[1536 + j] + b_hh[j];
    float hz = gp[1536 + j + 512] + b_hh[j + 512];
    float hn = gp[1536 + j + 1024] + b_hh[j + 1024];
    float r = 1.f / (1.f + expf(-(ir + hr)));
    float z = 1.f / (1.f + expf(-(iz + hz)));
    float n = tanhf(in_ + r * hn);
    float ho = (t == 0) ? 0.f : g_h[(t + 1) & 1][i];
    g_h[t & 1][i] = (1.f - z) * n + z * ho;
    if (i < NB) g_amax[t & 1][i] = 0ULL;
}

// ---------------- 3c) scores = h @ protos^T * ALPHA + BIAS ; UNK col ; argmax ------
// grid 126: blocks 0..124 cover 4000 proto cols (32 each), block 125 handles UNK col.
__global__ __launch_bounds__(256) void scores_kernel(const float* __restrict__ protos,
                                                     const int* __restrict__ plabel,
                                                     const float* __restrict__ pALPHA,
                                                     const float* __restrict__ pBIAS,
                                                     const float* __restrict__ pUNK,
                                                     float* __restrict__ out, int t) {
    int tid = threadIdx.x;
    int c0 = blockIdx.x * 32;
    const float* h = g_h[t & 1];

    if (c0 >= NPROTO) {  // UNK column only
        if (tid < NB) {
            float sc = pUNK[0];
            int cls = plabel[NPROTO];
            out[((size_t)tid * NT + t) * NCLASS + cls] = sc;
            unsigned long long p =
                ((unsigned long long)ford(sc) << 32) | (unsigned)(~(unsigned)cls);
            atomicMax(&g_amax[t & 1][tid], p);
        }
        return;
    }

    __shared__ unsigned long long bmax[64];
    __shared__ float Xs[64][17];
    __shared__ float Ws[32][17];
    if (tid < 64) bmax[tid] = 0ULL;

    int ty = tid >> 4, tx = tid & 15;
    float acc[4][2] = {};
    for (int k0 = 0; k0 < NC; k0 += 16) {
#pragma unroll
        for (int i = 0; i < 4; i++) {
            int lin = tid + i * 256, r = lin >> 4, k = lin & 15;
            Xs[r][k] = h[(size_t)r * NC + k0 + k];
        }
#pragma unroll
        for (int i = 0; i < 2; i++) {
            int lin = tid + i * 256, r = lin >> 4, k = lin & 15;
            Ws[r][k] = protos[(size_t)(c0 + r) * NC + k0 + k];
        }
        __syncthreads();
#pragma unroll
        for (int kk = 0; kk < 16; kk++) {
            float xv[4], wv[2];
#pragma unroll
            for (int m = 0; m < 4; m++) xv[m] = Xs[ty + 16 * m][kk];
#pragma unroll
            for (int n = 0; n < 2; n++) wv[n] = Ws[tx + 16 * n][kk];
#pragma unroll
            for (int m = 0; m < 4; m++)
#pragma unroll
                for (int n = 0; n < 2; n++) acc[m][n] += xv[m] * wv[n];
        }
        __syncthreads();
    }

    float AL = pALPHA[0], BI = pBIAS[0];
#pragma unroll
    for (int m = 0; m < 4; m++)
#pragma unroll
        for (int n = 0; n < 2; n++) {
            int row = ty + 16 * m;
            int c = c0 + tx + 16 * n;
            float sc = acc[m][n] * AL + BI;
            int cls = plabel[c];
            out[((size_t)row * NT + t) * NCLASS + cls] = sc;
            unsigned long long p =
                ((unsigned long long)ford(sc) << 32) | (unsigned)(~(unsigned)cls);
            atomicMax(&bmax[row], p);
        }
    __syncthreads();
    if (tid < 64) {
        unsigned long long v = bmax[tid];
        if (v) atomicMax(&g_amax[t & 1][tid], v);
    }
}

// ---------------- launch ------------------------------------------------------------
extern "C" void kernel_launch(void* const* d_in, const int* in_sizes, int n_in,
                              void* d_out, int out_size) {
    const float* feature = (const float*)d_in[0];
    const float* A       = (const float*)d_in[1];
    const float* protos  = (const float*)d_in[2];
    const float* semb    = (const float*)d_in[3];
    const float* STA     = (const float*)d_in[4];
    const float* UNK     = (const float*)d_in[5];
    const float* W_ih    = (const float*)d_in[6];
    const float* W_hh    = (const float*)d_in[7];
    const float* b_ih    = (const float*)d_in[8];
    const float* b_hh    = (const float*)d_in[9];
    const float* ALPHA   = (const float*)d_in[10];
    const float* BIAS    = (const float*)d_in[11];
    const float* UNK_SCR = (const float*)d_in[12];
    const int*   plabel  = (const int*)d_in[13];
    float* out = (float*)d_out;

    // out_attns = A reshaped (identity): straight device-to-device copy
    cudaMemcpyAsync(out + (size_t)NB * NT * NCLASS, A,
                    (size_t)NB * NT * NHW * sizeof(float), cudaMemcpyDeviceToDevice);

    int smem_pool = (NT * NHW + NHW) * (int)sizeof(float);  // ~99 KB
    cudaFuncSetAttribute(pool_kernel, cudaFuncAttributeMaxDynamicSharedMemorySize,
                         smem_pool);
    pool_kernel<<<dim3(NB, 8), 256, smem_pool>>>(feature, A);

    gic_kernel<<<dim3(32, 48), 256>>>(W_ih, b_ih);

    for (int t = 0; t < NT; t++) {
        gates_kernel<<<96, 256>>>(semb, UNK, STA, W_ih, W_hh, t);
        combine_kernel<<<128, 256>>>(b_hh, t);
        scores_kernel<<<126, 256>>>(protos, plabel, ALPHA, BIAS, UNK_SCR, out, t);
    }
}

// round 4
// speedup vs baseline: 2.0624x; 2.0624x over previous
#include <cuda_runtime.h>
#include <cstdint>

#define NB 64
#define NC 512
#define NHW 768
#define NT 32
#define NPROTO 4000
#define NCLASS 4001

// ---------------- scratch (static device globals; no allocation) ----------------
__device__ __align__(16) float g_C[NT * NB * NC];        // pooled features [t][b][c]
__device__ __align__(16) float g_GIC[NT * NB * 3 * NC];  // C@Wihc^T + b_ih
__device__ __align__(16) float g_GP[NB * 6 * NC];        // gi_prev(1536) | gh(1536)
__device__ __align__(16) float g_h[2][NB * NC];          // double-buffered hidden
__device__ unsigned long long g_amax[2][NB];             // packed (ord_val<<32 | ~cls)
__device__ unsigned g_bar_cnt = 0;
__device__ unsigned g_bar_gen = 0;

__device__ __forceinline__ unsigned ford(float f) {
    unsigned u = __float_as_uint(f);
    return (u & 0x80000000u) ? ~u : (u | 0x80000000u);
}
__device__ __forceinline__ unsigned long long packsc(float sc, int cls) {
    return ((unsigned long long)ford(sc) << 32) | (unsigned)(~(unsigned)cls);
}

// grid-wide barrier: count + generation, release/acquire via threadfence.
// Generation is monotonic across graph replays; count self-resets each use.
__device__ __forceinline__ void grid_barrier(int nblk) {
    __syncthreads();
    if (threadIdx.x == 0) {
        __threadfence();
        volatile unsigned* vgen = &g_bar_gen;
        unsigned gen = *vgen;
        unsigned prev = atomicAdd(&g_bar_cnt, 1u);
        if (prev == (unsigned)(nblk - 1)) {
            g_bar_cnt = 0;
            __threadfence();
            atomicAdd(&g_bar_gen, 1u);
        } else {
            while (*vgen == gen) __nanosleep(32);
        }
        __threadfence();
    }
    __syncthreads();
}

// 64(M) x 32(N) tile GEMM core, K-chunks of 32 floats, float4 smem staging.
// 512 threads: ty=tid>>4 (M rows ty, ty+32), tx=tid&15 (N cols tx, tx+16).
template <class XF, class WF>
__device__ __forceinline__ void gemm_tile(const XF& xf, const WF& wf, int kTot,
                                          float4* Xs4, float4* Ws4, float acc[2][2]) {
    const int tid = threadIdx.x;
    const int ty = tid >> 4, tx = tid & 15;
    const int lr = tid >> 3, lk = tid & 7;  // X: 64 rows x 8 f4; W: 32 rows x 8 f4
    acc[0][0] = acc[0][1] = acc[1][0] = acc[1][1] = 0.f;
    for (int k0 = 0; k0 < kTot; k0 += 32) {
        __syncthreads();
        Xs4[lr * 9 + lk] = xf(lr, k0 + lk * 4);
        if (tid < 256) Ws4[lr * 9 + lk] = wf(lr, k0 + lk * 4);
        __syncthreads();
#pragma unroll
        for (int kq = 0; kq < 8; kq++) {
            float4 x0 = Xs4[ty * 9 + kq];
            float4 x1 = Xs4[(ty + 32) * 9 + kq];
            float4 w0 = Ws4[tx * 9 + kq];
            float4 w1 = Ws4[(tx + 16) * 9 + kq];
            acc[0][0] += x0.x * w0.x + x0.y * w0.y + x0.z * w0.z + x0.w * w0.w;
            acc[0][1] += x0.x * w1.x + x0.y * w1.y + x0.z * w1.z + x0.w * w1.w;
            acc[1][0] += x1.x * w0.x + x1.y * w0.y + x1.z * w0.z + x1.w * w0.w;
            acc[1][1] += x1.x * w1.x + x1.y * w1.y + x1.z * w1.z + x1.w * w1.w;
        }
    }
}

__global__ __launch_bounds__(512, 1) void mega_kernel(
    const float* __restrict__ feature, const float* __restrict__ A,
    const float* __restrict__ protos, const float* __restrict__ semb,
    const float* __restrict__ STA, const float* __restrict__ UNK,
    const float* __restrict__ W_ih, const float* __restrict__ W_hh,
    const float* __restrict__ b_ih, const float* __restrict__ b_hh,
    const float* __restrict__ pALPHA, const float* __restrict__ pBIAS,
    const float* __restrict__ pUNK, const int* __restrict__ plabel,
    float* __restrict__ out, int nblk) {
    __shared__ float4 Xs4[64 * 9];
    __shared__ float4 Ws4[32 * 9];
    __shared__ int s_idx[64];
    __shared__ unsigned long long bmax[64];
    const int tid = threadIdx.x, blk = blockIdx.x;
    const int ty = tid >> 4, tx = tid & 15;

    // ---- phase 1: pool. 512 tiles: (b, cch). tile = 64 channels x 32 timesteps, K=768
    for (int tile = blk; tile < 512; tile += nblk) {
        int b = tile >> 3, cch = tile & 7;
        const float* xb = feature + ((size_t)b * NC + cch * 64) * NHW;
        const float* wb = A + (size_t)b * NT * NHW;
        float acc[2][2];
        gemm_tile([&](int r, int k) { return *(const float4*)(xb + (size_t)r * NHW + k); },
                  [&](int r, int k) { return *(const float4*)(wb + (size_t)r * NHW + k); },
                  NHW, Xs4, Ws4, acc);
#pragma unroll
        for (int m = 0; m < 2; m++)
#pragma unroll
            for (int n = 0; n < 2; n++) {
                int c = cch * 64 + ty + 32 * m;
                int t = tx + 16 * n;
                g_C[((size_t)t * NB + b) * NC + c] = acc[m][n];
            }
    }
    grid_barrier(nblk);

    // ---- phase 2: GIC = C2d[2048,512] @ Wihc^T + b_ih. 1536 tiles (32 mt x 48 nt)
    for (int tile = blk; tile < 1536; tile += nblk) {
        int mt = tile / 48, nt = tile % 48;
        const float* xb = g_C + (size_t)mt * 64 * NC;
        const float* wb = W_ih + (size_t)nt * 32 * (2 * NC);
        float acc[2][2];
        gemm_tile([&](int r, int k) { return *(const float4*)(xb + (size_t)r * NC + k); },
                  [&](int r, int k) { return *(const float4*)(wb + (size_t)r * (2 * NC) + k); },
                  NC, Xs4, Ws4, acc);
#pragma unroll
        for (int m = 0; m < 2; m++)
#pragma unroll
            for (int n = 0; n < 2; n++) {
                int row = mt * 64 + ty + 32 * m;
                int g = nt * 32 + tx + 16 * n;
                g_GIC[(size_t)row * 1536 + g] = acc[m][n] + b_ih[g];
            }
    }
    grid_barrier(nblk);

    const float AL = pALPHA[0], BI = pBIAS[0], USCR = pUNK[0];

    // ---- time scan ----
    for (int t = 0; t < NT; t++) {
        const int cur = t & 1, prv = cur ^ 1;

        // --- gates: GP[64][3072]. 96 tiles of 64x32, K=512
        for (int tile = blk; tile < 96; tile += nblk) {
            int n0 = tile * 32;
            bool isP = (n0 < 1536);
            if (!isP && t == 0) {  // h_old == 0 -> gh part exactly 0
#pragma unroll
                for (int m = 0; m < 2; m++)
#pragma unroll
                    for (int n = 0; n < 2; n++)
                        g_GP[(size_t)(ty + 32 * m) * 3072 + n0 + tx + 16 * n] = 0.f;
                continue;
            }
            float acc[2][2];
            if (isP) {
                const float* wb = W_ih + (size_t)n0 * (2 * NC) + NC;
                if (t == 0) {
                    gemm_tile([&](int r, int k) { return *(const float4*)(STA + k); },
                              [&](int r, int k) { return *(const float4*)(wb + (size_t)r * (2 * NC) + k); },
                              NC, Xs4, Ws4, acc);
                } else {
                    if (tid < 64) {
                        unsigned long long p = g_amax[prv][tid];
                        s_idx[tid] = (int)(~(unsigned)(p & 0xffffffffULL));
                    }
                    // first __syncthreads inside gemm_tile publishes s_idx
                    gemm_tile([&](int r, int k) {
                                  int idx = s_idx[r];
                                  const float* p = (idx < NPROTO) ? semb + (size_t)idx * NC : UNK;
                                  return *(const float4*)(p + k);
                              },
                              [&](int r, int k) { return *(const float4*)(wb + (size_t)r * (2 * NC) + k); },
                              NC, Xs4, Ws4, acc);
                }
            } else {
                const float* hb = g_h[prv];
                const float* wb = W_hh + (size_t)(n0 - 1536) * NC;
                gemm_tile([&](int r, int k) { return *(const float4*)(hb + (size_t)r * NC + k); },
                          [&](int r, int k) { return *(const float4*)(wb + (size_t)r * NC + k); },
                          NC, Xs4, Ws4, acc);
            }
#pragma unroll
            for (int m = 0; m < 2; m++)
#pragma unroll
                for (int n = 0; n < 2; n++)
                    g_GP[(size_t)(ty + 32 * m) * 3072 + n0 + tx + 16 * n] = acc[m][n];
        }
        grid_barrier(nblk);

        // --- combine: h_new, and reset this step's argmax slot
        for (int i = blk * 512 + tid; i < NB * NC; i += nblk * 512) {
            int b = i >> 9, j = i & 511;
            const float* gic = g_GIC + ((size_t)t * NB + b) * 1536;
            const float* gp = g_GP + (size_t)b * 3072;
            float ir = gic[j] + gp[j];
            float iz = gic[j + 512] + gp[j + 512];
            float in_ = gic[j + 1024] + gp[j + 1024];
            float hr = gp[1536 + j] + b_hh[j];
            float hz = gp[1536 + j + 512] + b_hh[j + 512];
            float hn = gp[1536 + j + 1024] + b_hh[j + 1024];
            float r = 1.f / (1.f + expf(-(ir + hr)));
            float z = 1.f / (1.f + expf(-(iz + hz)));
            float n = tanhf(in_ + r * hn);
            float ho = (t == 0) ? 0.f : g_h[prv][i];
            g_h[cur][i] = (1.f - z) * n + z * ho;
        }
        if (blk == 0 && tid < 64) g_amax[cur][tid] = 0ULL;
        grid_barrier(nblk);

        // --- scores: 125 GEMM tiles (4000 cols) + tile 125 = UNK column
        const float* hb = g_h[cur];
        for (int tile = blk; tile < 126; tile += nblk) {
            if (tile == 125) {
                if (tid < 64) {
                    int cls = plabel[NPROTO];
                    out[((size_t)tid * NT + t) * NCLASS + cls] = USCR;
                    atomicMax(&g_amax[cur][tid], packsc(USCR, cls));
                }
                continue;
            }
            __syncthreads();
            if (tid < 64) bmax[tid] = 0ULL;
            const float* wb = protos + (size_t)tile * 32 * NC;
            float acc[2][2];
            gemm_tile([&](int r, int k) { return *(const float4*)(hb + (size_t)r * NC + k); },
                      [&](int r, int k) { return *(const float4*)(wb + (size_t)r * NC + k); },
                      NC, Xs4, Ws4, acc);
#pragma unroll
            for (int m = 0; m < 2; m++)
#pragma unroll
                for (int n = 0; n < 2; n++) {
                    int row = ty + 32 * m;
                    int c = tile * 32 + tx + 16 * n;
                    float sc = acc[m][n] * AL + BI;
                    int cls = plabel[c];
                    out[((size_t)row * NT + t) * NCLASS + cls] = sc;
                    atomicMax(&bmax[row], packsc(sc, cls));
                }
            __syncthreads();
            if (tid < 64) {
                unsigned long long v = bmax[tid];
                if (v) atomicMax(&g_amax[cur][tid], v);
            }
        }
        grid_barrier(nblk);
    }
}

// ---------------- launch ------------------------------------------------------------
extern "C" void kernel_launch(void* const* d_in, const int* in_sizes, int n_in,
                              void* d_out, int out_size) {
    const float* feature = (const float*)d_in[0];
    const float* A       = (const float*)d_in[1];
    const float* protos  = (const float*)d_in[2];
    const float* semb    = (const float*)d_in[3];
    const float* STA     = (const float*)d_in[4];
    const float* UNK     = (const float*)d_in[5];
    const float* W_ih    = (const float*)d_in[6];
    const float* W_hh    = (const float*)d_in[7];
    const float* b_ih    = (const float*)d_in[8];
    const float* b_hh    = (const float*)d_in[9];
    const float* ALPHA   = (const float*)d_in[10];
    const float* BIAS    = (const float*)d_in[11];
    const float* UNK_SCR = (const float*)d_in[12];
    const int*   plabel  = (const int*)d_in[13];
    float* out = (float*)d_out;

    int dev = 0;
    cudaGetDevice(&dev);
    int nsm = 0;
    cudaDeviceGetAttribute(&nsm, cudaDevAttrMultiProcessorCount, dev);
    if (nsm < 1) nsm = 1;

    // out_attns = A reshaped (identity): straight device-to-device copy
    cudaMemcpyAsync(out + (size_t)NB * NT * NCLASS, A,
                    (size_t)NB * NT * NHW * sizeof(float), cudaMemcpyDeviceToDevice);

    mega_kernel<<<nsm, 512>>>(feature, A, protos, semb, STA, UNK, W_ih, W_hh,
                              b_ih, b_hh, ALPHA, BIAS, UNK_SCR, plabel, out, nsm);
}

// round 5
// speedup vs baseline: 2.7411x; 1.3291x over previous
#include <cuda_runtime.h>
#include <cstdint>

#define NB 64
#define NC 512
#define NHW 768
#define NT 32
#define NPROTO 4000
#define NCLASS 4001

// ---------------- scratch (static device globals; no allocation) ----------------
__device__ __align__(16) float g_C[NT * NB * NC];        // pooled features [t][b][c]
__device__ __align__(16) float g_GIC[NT * NB * 3 * NC];  // C@Wihc^T + b_ih
__device__ __align__(16) float g_GP[NB * 6 * NC];        // gi_prev(1536) | gh(1536)
__device__ __align__(16) float g_h[2][NB * NC];          // double-buffered hidden
__device__ unsigned long long g_amax[2][NB];             // packed (ord_val<<32 | ~cls)
__device__ unsigned g_bar_cnt = 0;
__device__ unsigned g_bar_gen = 0;

__device__ __forceinline__ unsigned ford(float f) {
    unsigned u = __float_as_uint(f);
    return (u & 0x80000000u) ? ~u : (u | 0x80000000u);
}
__device__ __forceinline__ unsigned long long packsc(float sc, int cls) {
    return ((unsigned long long)ford(sc) << 32) | (unsigned)(~(unsigned)cls);
}

// grid-wide barrier: count + generation, release/acquire via threadfence.
__device__ __forceinline__ void grid_barrier(int nblk) {
    __syncthreads();
    if (threadIdx.x == 0) {
        __threadfence();
        volatile unsigned* vgen = &g_bar_gen;
        unsigned gen = *vgen;
        unsigned prev = atomicAdd(&g_bar_cnt, 1u);
        if (prev == (unsigned)(nblk - 1)) {
            g_bar_cnt = 0;
            __threadfence();
            atomicAdd(&g_bar_gen, 1u);
        } else {
            while (*vgen == gen) __nanosleep(32);
        }
        __threadfence();
    }
    __syncthreads();
}

// 64(M) x 32(N) tile GEMM, K-chunks of 32 floats, DOUBLE-BUFFERED smem staging,
// one __syncthreads per chunk, gmem prefetch overlapped with compute.
// 16 independent accumulator chains (float4 per output), summed at epilogue.
// 512 threads: ty=tid>>4 (rows ty, ty+32), tx=tid&15 (cols tx, tx+16).
// Xs4: 2*576 float4, Ws4: 2*288 float4.
template <class XF, class WF>
__device__ __forceinline__ void gemm_tile(const XF& xf, const WF& wf, int kTot,
                                          float4* Xs4, float4* Ws4,
                                          float4 acc[2][2]) {
    const int tid = threadIdx.x;
    const int ty = tid >> 4, tx = tid & 15;
    const int lr = tid >> 3, lk = tid & 7;  // X: 64 rows x 8 f4; W: 32 rows x 8 f4
#pragma unroll
    for (int m = 0; m < 2; m++)
#pragma unroll
        for (int n = 0; n < 2; n++) acc[m][n] = make_float4(0.f, 0.f, 0.f, 0.f);

    const int nch = kTot >> 5;
    // prologue: chunk 0 -> regs -> smem buf 0
    float4 px = xf(lr, lk * 4);
    float4 pw;
    if (tid < 256) pw = wf(lr, lk * 4);
    Xs4[lr * 9 + lk] = px;
    if (tid < 256) Ws4[lr * 9 + lk] = pw;
    __syncthreads();

    for (int c = 0; c < nch; c++) {
        const bool more = (c + 1 < nch);
        if (more) {  // prefetch next chunk while computing current
            px = xf(lr, (c + 1) * 32 + lk * 4);
            if (tid < 256) pw = wf(lr, (c + 1) * 32 + lk * 4);
        }
        const float4* Xb = Xs4 + (c & 1) * 576;
        const float4* Wb = Ws4 + (c & 1) * 288;
#pragma unroll
        for (int kq = 0; kq < 8; kq++) {
            float4 x0 = Xb[ty * 9 + kq];
            float4 x1 = Xb[(ty + 32) * 9 + kq];
            float4 w0 = Wb[tx * 9 + kq];
            float4 w1 = Wb[(tx + 16) * 9 + kq];
            acc[0][0].x += x0.x * w0.x; acc[0][0].y += x0.y * w0.y;
            acc[0][0].z += x0.z * w0.z; acc[0][0].w += x0.w * w0.w;
            acc[0][1].x += x0.x * w1.x; acc[0][1].y += x0.y * w1.y;
            acc[0][1].z += x0.z * w1.z; acc[0][1].w += x0.w * w1.w;
            acc[1][0].x += x1.x * w0.x; acc[1][0].y += x1.y * w0.y;
            acc[1][0].z += x1.z * w0.z; acc[1][0].w += x1.w * w0.w;
            acc[1][1].x += x1.x * w1.x; acc[1][1].y += x1.y * w1.y;
            acc[1][1].z += x1.z * w1.z; acc[1][1].w += x1.w * w1.w;
        }
        if (more) {  // store prefetch into the other buffer; single sync
            const int nb = (c + 1) & 1;
            Xs4[nb * 576 + lr * 9 + lk] = px;
            if (tid < 256) Ws4[nb * 288 + lr * 9 + lk] = pw;
            __syncthreads();
        }
    }
}
__device__ __forceinline__ float acc_sum(const float4& a) {
    return (a.x + a.y) + (a.z + a.w);
}

__global__ __launch_bounds__(512, 1) void mega_kernel(
    const float* __restrict__ feature, const float* __restrict__ A,
    const float* __restrict__ protos, const float* __restrict__ semb,
    const float* __restrict__ STA, const float* __restrict__ UNK,
    const float* __restrict__ W_ih, const float* __restrict__ W_hh,
    const float* __restrict__ b_ih, const float* __restrict__ b_hh,
    const float* __restrict__ pALPHA, const float* __restrict__ pBIAS,
    const float* __restrict__ pUNK, const int* __restrict__ plabel,
    float* __restrict__ out, int nblk) {
    __shared__ float4 Xs4[2 * 576];
    __shared__ float4 Ws4[2 * 288];
    __shared__ int s_idx[64];
    __shared__ unsigned long long bmax[64];
    const int tid = threadIdx.x, blk = blockIdx.x;
    const int ty = tid >> 4, tx = tid & 15;

    // ---- phase 1: pool. 512 tiles (b, cch): 64 channels x 32 timesteps, K=768
    for (int tile = blk; tile < 512; tile += nblk) {
        int b = tile >> 3, cch = tile & 7;
        const float* xb = feature + ((size_t)b * NC + cch * 64) * NHW;
        const float* wb = A + (size_t)b * NT * NHW;
        float4 acc[2][2];
        gemm_tile([&](int r, int k) { return *(const float4*)(xb + (size_t)r * NHW + k); },
                  [&](int r, int k) { return *(const float4*)(wb + (size_t)r * NHW + k); },
                  NHW, Xs4, Ws4, acc);
        __syncthreads();
#pragma unroll
        for (int m = 0; m < 2; m++)
#pragma unroll
            for (int n = 0; n < 2; n++) {
                int c = cch * 64 + ty + 32 * m;
                int t = tx + 16 * n;
                g_C[((size_t)t * NB + b) * NC + c] = acc_sum(acc[m][n]);
            }
    }
    grid_barrier(nblk);

    // ---- phase 2: GIC = C2d[2048,512] @ Wihc^T + b_ih. 1536 tiles (32 mt x 48 nt)
    for (int tile = blk; tile < 1536; tile += nblk) {
        int mt = tile / 48, nt = tile % 48;
        const float* xb = g_C + (size_t)mt * 64 * NC;
        const float* wb = W_ih + (size_t)nt * 32 * (2 * NC);
        float4 acc[2][2];
        gemm_tile([&](int r, int k) { return *(const float4*)(xb + (size_t)r * NC + k); },
                  [&](int r, int k) { return *(const float4*)(wb + (size_t)r * (2 * NC) + k); },
                  NC, Xs4, Ws4, acc);
        __syncthreads();
#pragma unroll
        for (int m = 0; m < 2; m++)
#pragma unroll
            for (int n = 0; n < 2; n++) {
                int row = mt * 64 + ty + 32 * m;
                int g = nt * 32 + tx + 16 * n;
                g_GIC[(size_t)row * 1536 + g] = acc_sum(acc[m][n]) + b_ih[g];
            }
    }
    grid_barrier(nblk);

    const float AL = pALPHA[0], BI = pBIAS[0], USCR = pUNK[0];

    // ---- time scan ----
    for (int t = 0; t < NT; t++) {
        const int cur = t & 1, prv = cur ^ 1;

        // --- gates: GP[64][3072]. 96 tiles of 64x32, K=512
        for (int tile = blk; tile < 96; tile += nblk) {
            int n0 = tile * 32;
            bool isP = (n0 < 1536);
            if (!isP && t == 0) {  // h_old == 0 -> gh part exactly 0
#pragma unroll
                for (int m = 0; m < 2; m++)
#pragma unroll
                    for (int n = 0; n < 2; n++)
                        g_GP[(size_t)(ty + 32 * m) * 3072 + n0 + tx + 16 * n] = 0.f;
                continue;
            }
            float4 acc[2][2];
            if (isP) {
                const float* wb = W_ih + (size_t)n0 * (2 * NC) + NC;
                if (t == 0) {
                    gemm_tile([&](int r, int k) { return *(const float4*)(STA + k); },
                              [&](int r, int k) { return *(const float4*)(wb + (size_t)r * (2 * NC) + k); },
                              NC, Xs4, Ws4, acc);
                } else {
                    if (tid < 64) {
                        unsigned long long p = g_amax[prv][tid];
                        s_idx[tid] = (int)(~(unsigned)(p & 0xffffffffULL));
                    }
                    __syncthreads();  // publish s_idx before prologue prefetch
                    gemm_tile([&](int r, int k) {
                                  int idx = s_idx[r];
                                  const float* p = (idx < NPROTO) ? semb + (size_t)idx * NC : UNK;
                                  return *(const float4*)(p + k);
                              },
                              [&](int r, int k) { return *(const float4*)(wb + (size_t)r * (2 * NC) + k); },
                              NC, Xs4, Ws4, acc);
                }
            } else {
                const float* hb = g_h[prv];
                const float* wb = W_hh + (size_t)(n0 - 1536) * NC;
                gemm_tile([&](int r, int k) { return *(const float4*)(hb + (size_t)r * NC + k); },
                          [&](int r, int k) { return *(const float4*)(wb + (size_t)r * NC + k); },
                          NC, Xs4, Ws4, acc);
            }
            __syncthreads();
#pragma unroll
            for (int m = 0; m < 2; m++)
#pragma unroll
                for (int n = 0; n < 2; n++)
                    g_GP[(size_t)(ty + 32 * m) * 3072 + n0 + tx + 16 * n] =
                        acc_sum(acc[m][n]);
        }
        grid_barrier(nblk);

        // --- combine: h_new, and reset this step's argmax slot
        for (int i = blk * 512 + tid; i < NB * NC; i += nblk * 512) {
            int b = i >> 9, j = i & 511;
            const float* gic = g_GIC + ((size_t)t * NB + b) * 1536;
            const float* gp = g_GP + (size_t)b * 3072;
            float ir = gic[j] + gp[j];
            float iz = gic[j + 512] + gp[j + 512];
            float in_ = gic[j + 1024] + gp[j + 1024];
            float hr = gp[1536 + j] + b_hh[j];
            float hz = gp[1536 + j + 512] + b_hh[j + 512];
            float hn = gp[1536 + j + 1024] + b_hh[j + 1024];
            float r = 1.f / (1.f + expf(-(ir + hr)));
            float z = 1.f / (1.f + expf(-(iz + hz)));
            float n = tanhf(in_ + r * hn);
            float ho = (t == 0) ? 0.f : g_h[prv][i];
            g_h[cur][i] = (1.f - z) * n + z * ho;
        }
        if (blk == 0 && tid < 64) g_amax[cur][tid] = 0ULL;
        grid_barrier(nblk);

        // --- scores: 125 GEMM tiles (4000 cols) + tile 125 = UNK column
        const float* hb = g_h[cur];
        for (int tile = blk; tile < 126; tile += nblk) {
            if (tile == 125) {
                if (tid < 64) {
                    int cls = plabel[NPROTO];
                    out[((size_t)tid * NT + t) * NCLASS + cls] = USCR;
                    atomicMax(&g_amax[cur][tid], packsc(USCR, cls));
                }
                continue;
            }
            if (tid < 64) bmax[tid] = 0ULL;
            __syncthreads();  // publish bmax reset (also isolates smem reuse)
            const float* wb = protos + (size_t)tile * 32 * NC;
            float4 acc[2][2];
            gemm_tile([&](int r, int k) { return *(const float4*)(hb + (size_t)r * NC + k); },
                      [&](int r, int k) { return *(const float4*)(wb + (size_t)r * NC + k); },
                      NC, Xs4, Ws4, acc);
#pragma unroll
            for (int m = 0; m < 2; m++)
#pragma unroll
                for (int n = 0; n < 2; n++) {
                    int row = ty + 32 * m;
                    int c = tile * 32 + tx + 16 * n;
                    float sc = acc_sum(acc[m][n]) * AL + BI;
                    int cls = plabel[c];
                    out[((size_t)row * NT + t) * NCLASS + cls] = sc;
                    atomicMax(&bmax[row], packsc(sc, cls));
                }
            __syncthreads();
            if (tid < 64) {
                unsigned long long v = bmax[tid];
                if (v) atomicMax(&g_amax[cur][tid], v);
            }
            __syncthreads();  // bmax fully consumed before next tile resets it
        }
        grid_barrier(nblk);
    }
}

// ---------------- launch ------------------------------------------------------------
extern "C" void kernel_launch(void* const* d_in, const int* in_sizes, int n_in,
                              void* d_out, int out_size) {
    const float* feature = (const float*)d_in[0];
    const float* A       = (const float*)d_in[1];
    const float* protos  = (const float*)d_in[2];
    const float* semb    = (const float*)d_in[3];
    const float* STA     = (const float*)d_in[4];
    const float* UNK     = (const float*)d_in[5];
    const float* W_ih    = (const float*)d_in[6];
    const float* W_hh    = (const float*)d_in[7];
    const float* b_ih    = (const float*)d_in[8];
    const float* b_hh    = (const float*)d_in[9];
    const float* ALPHA   = (const float*)d_in[10];
    const float* BIAS    = (const float*)d_in[11];
    const float* UNK_SCR = (const float*)d_in[12];
    const int*   plabel  = (const int*)d_in[13];
    float* out = (float*)d_out;

    int dev = 0;
    cudaGetDevice(&dev);
    int nsm = 0;
    cudaDeviceGetAttribute(&nsm, cudaDevAttrMultiProcessorCount, dev);
    if (nsm < 1) nsm = 1;

    // out_attns = A reshaped (identity): straight device-to-device copy
    cudaMemcpyAsync(out + (size_t)NB * NT * NCLASS, A,
                    (size_t)NB * NT * NHW * sizeof(float), cudaMemcpyDeviceToDevice);

    mega_kernel<<<nsm, 512>>>(feature, A, protos, semb, STA, UNK, W_ih, W_hh,
                              b_ih, b_hh, ALPHA, BIAS, UNK_SCR, plabel, out, nsm);
}

// round 8
// speedup vs baseline: 2.8831x; 1.0518x over previous
#include <cuda_runtime.h>
#include <cstdint>

#define NB 64
#define NC 512
#define NHW 768
#define NT 32
#define NPROTO 4000
#define NCLASS 4001
#define NGRP 4

// ---------------- scratch (static device globals; no allocation) ----------------
__device__ __align__(16) float g_C[NT * NB * NC];        // pooled features [t][b][c]
__device__ __align__(16) float g_GIC[NT * NB * 3 * NC];  // C@Wihc^T + b_ih
__device__ __align__(16) float g_GP[NB * 6 * NC];        // gi_prev(1536) | gh(1536)
__device__ __align__(16) float g_h[2][NB * NC];          // double-buffered hidden
__device__ unsigned long long g_amax[2][NB];             // packed (ord_val<<32 | ~cls)
__device__ unsigned g_bar_cnt = 0;
__device__ unsigned g_bar_gen = 0;

__device__ __forceinline__ unsigned ford(float f) {
    unsigned u = __float_as_uint(f);
    return (u & 0x80000000u) ? ~u : (u | 0x80000000u);
}
__device__ __forceinline__ unsigned long long packsc(float sc, int cls) {
    return ((unsigned long long)ford(sc) << 32) | (unsigned)(~(unsigned)cls);
}

// grid-wide barrier: count + generation, release/acquire via threadfence.
__device__ __forceinline__ void grid_barrier(int nblk) {
    __syncthreads();
    if (threadIdx.x == 0) {
        __threadfence();
        volatile unsigned* vgen = &g_bar_gen;
        unsigned gen = *vgen;
        unsigned prev = atomicAdd(&g_bar_cnt, 1u);
        if (prev == (unsigned)(nblk - 1)) {
            g_bar_cnt = 0;
            __threadfence();
            atomicAdd(&g_bar_gen, 1u);
        } else {
            while (*vgen == gen) __nanosleep(32);
        }
        __threadfence();
    }
    __syncthreads();
}

// named barrier across one 128-thread group (ids 1..4)
#define GBAR(id) asm volatile("bar.sync %0, 128;" ::"r"(id) : "memory")

// 64(M) x 32(N) tile GEMM per 128-thread group. 4x4 register tile (strided
// mapping m=tr+16i, n=tc+8j -> conflict-free lane-adjacent LDS.128), K-chunks
// of 32 floats, double-buffered smem, one group barrier per chunk.
// Xg: 2*576 float4 (64 rows x 9-pitch), Wg: 2*288 float4 (32 rows x 9-pitch).
template <class XF, class WF>
__device__ __forceinline__ void gemm4(const XF& xf, const WF& wf, int nch,
                                      float4* __restrict__ Xg,
                                      float4* __restrict__ Wg, int barid,
                                      float acc[4][4]) {
    const int gtid = threadIdx.x & 127;
    const int tr = gtid >> 3, tc = gtid & 7;  // compute roles
    const int xr = gtid >> 3, xc = gtid & 7;  // load roles
#pragma unroll
    for (int i = 0; i < 4; i++)
#pragma unroll
        for (int j = 0; j < 4; j++) acc[i][j] = 0.f;

    float4 px[4], pw[2];
#pragma unroll
    for (int i = 0; i < 4; i++) px[i] = xf(xr + i * 16, xc * 4);
#pragma unroll
    for (int j = 0; j < 2; j++) pw[j] = wf(xr + j * 16, xc * 4);
#pragma unroll
    for (int i = 0; i < 4; i++) Xg[(xr + i * 16) * 9 + xc] = px[i];
#pragma unroll
    for (int j = 0; j < 2; j++) Wg[(xr + j * 16) * 9 + xc] = pw[j];
    GBAR(barid);

    for (int c = 0; c < nch; c++) {
        const bool more = (c + 1 < nch);
        if (more) {
            const int k0 = (c + 1) * 32;
#pragma unroll
            for (int i = 0; i < 4; i++) px[i] = xf(xr + i * 16, k0 + xc * 4);
#pragma unroll
            for (int j = 0; j < 2; j++) pw[j] = wf(xr + j * 16, k0 + xc * 4);
        }
        const float4* Xb = Xg + (c & 1) * 576;
        const float4* Wb = Wg + (c & 1) * 288;
#pragma unroll
        for (int kq = 0; kq < 8; kq++) {
            float4 xv[4], wv[4];
#pragma unroll
            for (int i = 0; i < 4; i++) xv[i] = Xb[(tr + 16 * i) * 9 + kq];
#pragma unroll
            for (int j = 0; j < 4; j++) wv[j] = Wb[(tc + 8 * j) * 9 + kq];
#pragma unroll
            for (int i = 0; i < 4; i++)
#pragma unroll
                for (int j = 0; j < 4; j++) {
                    acc[i][j] += xv[i].x * wv[j].x;
                    acc[i][j] += xv[i].y * wv[j].y;
                    acc[i][j] += xv[i].z * wv[j].z;
                    acc[i][j] += xv[i].w * wv[j].w;
                }
        }
        if (more) {
            const int nb = (c + 1) & 1;
#pragma unroll
            for (int i = 0; i < 4; i++) Xg[nb * 576 + (xr + i * 16) * 9 + xc] = px[i];
#pragma unroll
            for (int j = 0; j < 2; j++) Wg[nb * 288 + (xr + j * 16) * 9 + xc] = pw[j];
            GBAR(barid);
        }
    }
    // nch is even (16 or 24): last compute buffer is 1, next prologue writes 0,
    // and the prologue GBAR orders reuse -> no trailing barrier needed.
}

__global__ __launch_bounds__(512, 1) void mega_kernel(
    const float* __restrict__ feature, const float* __restrict__ A,
    const float* __restrict__ protos, const float* __restrict__ semb,
    const float* __restrict__ STA, const float* __restrict__ UNK,
    const float* __restrict__ W_ih, const float* __restrict__ W_hh,
    const float* __restrict__ b_ih, const float* __restrict__ b_hh,
    const float* __restrict__ pALPHA, const float* __restrict__ pBIAS,
    const float* __restrict__ pUNK, const int* __restrict__ plabel,
    float* __restrict__ out, int nblk) {
    extern __shared__ unsigned char smem[];
    float4* sX = (float4*)smem;                       // [NGRP][2*576]
    float4* sW = sX + NGRP * 2 * 576;                 // [NGRP][2*288]
    unsigned long long* sbmax =
        (unsigned long long*)(sW + NGRP * 2 * 288);   // [NGRP][64]
    int* s_idx = (int*)(sbmax + NGRP * 64);           // [64]

    const int tid = threadIdx.x, blk = blockIdx.x;
    const int gid = tid >> 7, gtid = tid & 127;
    const int barid = gid + 1;
    const int tr = gtid >> 3, tc = gtid & 7;
    float4* Xg = sX + gid * 2 * 576;
    float4* Wg = sW + gid * 2 * 288;
    unsigned long long* bmax = sbmax + gid * 64;

    // ---- phase 1: pool. 512 tiles (b, cch): 64 channels x 32 timesteps, K=768
    for (int s = gid;; s += NGRP) {
        int tile = blk + s * nblk;
        if (tile >= 512) break;
        int b = tile >> 3, cch = tile & 7;
        const float* xb = feature + ((size_t)b * NC + cch * 64) * NHW;
        const float* wb = A + (size_t)b * NT * NHW;
        float acc[4][4];
        gemm4([&](int r, int k) { return *(const float4*)(xb + (size_t)r * NHW + k); },
              [&](int r, int k) { return *(const float4*)(wb + (size_t)r * NHW + k); },
              NHW / 32, Xg, Wg, barid, acc);
#pragma unroll
        for (int i = 0; i < 4; i++)
#pragma unroll
            for (int j = 0; j < 4; j++) {
                int c = cch * 64 + tr + 16 * i;
                int t = tc + 8 * j;
                g_C[((size_t)t * NB + b) * NC + c] = acc[i][j];
            }
        GBAR(barid);  // outputs drained before smem buffers are refilled
    }
    grid_barrier(nblk);

    // ---- phase 2: GIC = C2d[2048,512] @ Wihc^T + b_ih. 1536 tiles (32 mt x 48 nt)
    for (int s = gid;; s += NGRP) {
        int tile = blk + s * nblk;
        if (tile >= 1536) break;
        int mt = tile / 48, nt = tile % 48;
        const float* xb = g_C + (size_t)mt * 64 * NC;
        const float* wb = W_ih + (size_t)nt * 32 * (2 * NC);
        float acc[4][4];
        gemm4([&](int r, int k) { return *(const float4*)(xb + (size_t)r * NC + k); },
              [&](int r, int k) { return *(const float4*)(wb + (size_t)r * (2 * NC) + k); },
              NC / 32, Xg, Wg, barid, acc);
#pragma unroll
        for (int i = 0; i < 4; i++)
#pragma unroll
            for (int j = 0; j < 4; j++) {
                int row = mt * 64 + tr + 16 * i;
                int g = nt * 32 + tc + 8 * j;
                g_GIC[(size_t)row * 1536 + g] = acc[i][j] + b_ih[g];
            }
        GBAR(barid);
    }
    grid_barrier(nblk);

    const float AL = pALPHA[0], BI = pBIAS[0], USCR = pUNK[0];

    // ---- time scan ----
    for (int t = 0; t < NT; t++) {
        const int cur = t & 1, prv = cur ^ 1;

        // --- gates: GP[64][3072]. 96 tiles of 64x32, K=512
        if (t > 0) {
            if (tid < 64) {
                unsigned long long p = g_amax[prv][tid];
                s_idx[tid] = (int)(~(unsigned)(p & 0xffffffffULL));
            }
            __syncthreads();  // publish s_idx to all groups
        }
        for (int s = gid;; s += NGRP) {
            int tile = blk + s * nblk;
            if (tile >= 96) break;
            int n0 = tile * 32;
            bool isP = (n0 < 1536);
            if (!isP && t == 0) {  // h_old == 0 -> gh part exactly 0
#pragma unroll
                for (int i = 0; i < 4; i++)
#pragma unroll
                    for (int j = 0; j < 4; j++)
                        g_GP[(size_t)(tr + 16 * i) * 3072 + n0 + tc + 8 * j] = 0.f;
                continue;
            }
            float acc[4][4];
            if (isP) {
                const float* wb = W_ih + (size_t)n0 * (2 * NC) + NC;
                if (t == 0) {
                    gemm4([&](int r, int k) { return *(const float4*)(STA + k); },
                          [&](int r, int k) { return *(const float4*)(wb + (size_t)r * (2 * NC) + k); },
                          NC / 32, Xg, Wg, barid, acc);
                } else {
                    gemm4([&](int r, int k) {
                              int idx = s_idx[r];
                              const float* p = (idx < NPROTO) ? semb + (size_t)idx * NC : UNK;
                              return *(const float4*)(p + k);
                          },
                          [&](int r, int k) { return *(const float4*)(wb + (size_t)r * (2 * NC) + k); },
                          NC / 32, Xg, Wg, barid, acc);
                }
            } else {
                const float* hb = g_h[prv];
                const float* wb = W_hh + (size_t)(n0 - 1536) * NC;
                gemm4([&](int r, int k) { return *(const float4*)(hb + (size_t)r * NC + k); },
                      [&](int r, int k) { return *(const float4*)(wb + (size_t)r * NC + k); },
                      NC / 32, Xg, Wg, barid, acc);
            }
#pragma unroll
            for (int i = 0; i < 4; i++)
#pragma unroll
                for (int j = 0; j < 4; j++)
                    g_GP[(size_t)(tr + 16 * i) * 3072 + n0 + tc + 8 * j] = acc[i][j];
            GBAR(barid);
        }
        grid_barrier(nblk);

        // --- combine: h_new, and reset this step's argmax slot
        for (int i = blk * 512 + tid; i < NB * NC; i += nblk * 512) {
            int b = i >> 9, j = i & 511;
            const float* gic = g_GIC + ((size_t)t * NB + b) * 1536;
            const float* gp = g_GP + (size_t)b * 3072;
            float ir = gic[j] + gp[j];
            float iz = gic[j + 512] + gp[j + 512];
            float in_ = gic[j + 1024] + gp[j + 1024];
            float hr = gp[1536 + j] + b_hh[j];
            float hz = gp[1536 + j + 512] + b_hh[j + 512];
            float hn = gp[1536 + j + 1024] + b_hh[j + 1024];
            float r = 1.f / (1.f + expf(-(ir + hr)));
            float z = 1.f / (1.f + expf(-(iz + hz)));
            float n = tanhf(in_ + r * hn);
            float ho = (t == 0) ? 0.f : g_h[prv][i];
            g_h[cur][i] = (1.f - z) * n + z * ho;
        }
        if (blk == 0 && tid < 64) g_amax[cur][tid] = 0ULL;
        grid_barrier(nblk);

        // --- scores: 125 GEMM tiles (4000 cols) + tile 125 = UNK column
        const float* hb = g_h[cur];
        for (int s = gid;; s += NGRP) {
            int tile = blk + s * nblk;
            if (tile >= 126) break;
            if (tile == 125) {
                if (gtid < 64) {
                    int cls = plabel[NPROTO];
                    out[((size_t)gtid * NT + t) * NCLASS + cls] = USCR;
                    atomicMax(&g_amax[cur][gtid], packsc(USCR, cls));
                }
                continue;
            }
            if (gtid < 64) bmax[gtid] = 0ULL;  // published by prologue GBAR
            const float* wb = protos + (size_t)tile * 32 * NC;
            float acc[4][4];
            gemm4([&](int r, int k) { return *(const float4*)(hb + (size_t)r * NC + k); },
                  [&](int r, int k) { return *(const float4*)(wb + (size_t)r * NC + k); },
                  NC / 32, Xg, Wg, barid, acc);
#pragma unroll
            for (int i = 0; i < 4; i++) {
                int row = tr + 16 * i;
                unsigned long long lmax = 0ULL;
#pragma unroll
                for (int j = 0; j < 4; j++) {
                    int c = tile * 32 + tc + 8 * j;
                    float sc = acc[i][j] * AL + BI;
                    int cls = plabel[c];
                    out[((size_t)row * NT + t) * NCLASS + cls] = sc;
                    unsigned long long p = packsc(sc, cls);
                    if (p > lmax) lmax = p;
                }
                atomicMax(&bmax[row], lmax);
            }
            GBAR(barid);
            if (gtid < 64) {
                unsigned long long v = bmax[gtid];
                if (v) atomicMax(&g_amax[cur][gtid], v);
            }
            GBAR(barid);  // bmax consumed before next tile resets it
        }
        grid_barrier(nblk);
    }
}

// ---------------- launch ------------------------------------------------------------
extern "C" void kernel_launch(void* const* d_in, const int* in_sizes, int n_in,
                              void* d_out, int out_size) {
    const float* feature = (const float*)d_in[0];
    const float* A       = (const float*)d_in[1];
    const float* protos  = (const float*)d_in[2];
    const float* semb    = (const float*)d_in[3];
    const float* STA     = (const float*)d_in[4];
    const float* UNK     = (const float*)d_in[5];
    const float* W_ih    = (const float*)d_in[6];
    const float* W_hh    = (const float*)d_in[7];
    const float* b_ih    = (const float*)d_in[8];
    const float* b_hh    = (const float*)d_in[9];
    const float* ALPHA   = (const float*)d_in[10];
    const float* BIAS    = (const float*)d_in[11];
    const float* UNK_SCR = (const float*)d_in[12];
    const int*   plabel  = (const int*)d_in[13];
    float* out = (float*)d_out;

    int dev = 0;
    cudaGetDevice(&dev);
    int nsm = 0;
    cudaDeviceGetAttribute(&nsm, cudaDevAttrMultiProcessorCount, dev);
    if (nsm < 1) nsm = 1;

    // out_attns = A reshaped (identity): straight device-to-device copy
    cudaMemcpyAsync(out + (size_t)NB * NT * NCLASS, A,
                    (size_t)NB * NT * NHW * sizeof(float), cudaMemcpyDeviceToDevice);

    int smem_bytes = NGRP * 2 * 576 * 16 + NGRP * 2 * 288 * 16 + NGRP * 64 * 8 + 64 * 4;
    cudaFuncSetAttribute(mega_kernel, cudaFuncAttributeMaxDynamicSharedMemorySize,
                         smem_bytes);
    mega_kernel<<<nsm, 512, smem_bytes>>>(feature, A, protos, semb, STA, UNK, W_ih,
                                          W_hh, b_ih, b_hh, ALPHA, BIAS, UNK_SCR,
                                          plabel, out, nsm);
}